// round 2
// baseline (speedup 1.0000x reference)
#include <cuda_runtime.h>

// StructuredDeepLinear: 1000 Monarch layers, DIM=1024 (M=32 blocks of 32x32), BATCH=512.
//
// Sample-parallel persistent kernel: each CTA owns 4 samples, activations live in
// SMEM for all 1000 layers, weights stream GMEM(L2)->registers.
//
// SMEM convention (PAD=36 words/row, 16B-aligned, conflict-free both ways):
//   phase reads  in[p][r]  at src[p*36 + r]   -> float4 LDS.128, conflict-free
//   phase writes out[p][q] at dst[q*36 + p]   -> scalar STS, conflict-free
// so the Monarch block-transpose between phases is free (pure addressing).
//
// Thread map (512 thr): p = lane (block row), qg = q-group of 4, sg = sample pair.
// The two sg-groups issue identical weight LDGs -> L1 dedup, L2 traffic unchanged.

#define BATCHPER 4
#define NCTA     128   // 128 * 4 = 512 = BATCH
#define NTHREADS 512
#define DEPTH    1000
#define PAD      36
#define SROW     (32 * PAD)   // 1152 floats per sample per buffer

__device__ __forceinline__ void phase(const float* __restrict__ src,
                                      float*       __restrict__ dst,
                                      const float* __restrict__ W,
                                      int p, int qg, int sg)
{
    // acc[s][j]: s = sample within pair, j = q offset; q = qg*4 + j
    float acc[2][4];
#pragma unroll
    for (int s = 0; s < 2; ++s)
#pragma unroll
        for (int j = 0; j < 4; ++j) acc[s][j] = 0.0f;

    const float* wrow = W + p * 1024 + qg * 128;          // rows (q0+j): wrow + j*32
    const float* s0 = src + (2 * sg + 0) * SROW + p * PAD;
    const float* s1 = src + (2 * sg + 1) * SROW + p * PAD;

#pragma unroll
    for (int c = 0; c < 8; ++c) {                          // r-chunk of 4
        float4 w0 = *reinterpret_cast<const float4*>(wrow + 0 * 32 + c * 4);
        float4 w1 = *reinterpret_cast<const float4*>(wrow + 1 * 32 + c * 4);
        float4 w2 = *reinterpret_cast<const float4*>(wrow + 2 * 32 + c * 4);
        float4 w3 = *reinterpret_cast<const float4*>(wrow + 3 * 32 + c * 4);

        float4 a0 = *reinterpret_cast<const float4*>(s0 + c * 4);
        float4 a1 = *reinterpret_cast<const float4*>(s1 + c * 4);

        acc[0][0] = fmaf(a0.x, w0.x, acc[0][0]); acc[0][0] = fmaf(a0.y, w0.y, acc[0][0]);
        acc[0][0] = fmaf(a0.z, w0.z, acc[0][0]); acc[0][0] = fmaf(a0.w, w0.w, acc[0][0]);
        acc[0][1] = fmaf(a0.x, w1.x, acc[0][1]); acc[0][1] = fmaf(a0.y, w1.y, acc[0][1]);
        acc[0][1] = fmaf(a0.z, w1.z, acc[0][1]); acc[0][1] = fmaf(a0.w, w1.w, acc[0][1]);
        acc[0][2] = fmaf(a0.x, w2.x, acc[0][2]); acc[0][2] = fmaf(a0.y, w2.y, acc[0][2]);
        acc[0][2] = fmaf(a0.z, w2.z, acc[0][2]); acc[0][2] = fmaf(a0.w, w2.w, acc[0][2]);
        acc[0][3] = fmaf(a0.x, w3.x, acc[0][3]); acc[0][3] = fmaf(a0.y, w3.y, acc[0][3]);
        acc[0][3] = fmaf(a0.z, w3.z, acc[0][3]); acc[0][3] = fmaf(a0.w, w3.w, acc[0][3]);

        acc[1][0] = fmaf(a1.x, w0.x, acc[1][0]); acc[1][0] = fmaf(a1.y, w0.y, acc[1][0]);
        acc[1][0] = fmaf(a1.z, w0.z, acc[1][0]); acc[1][0] = fmaf(a1.w, w0.w, acc[1][0]);
        acc[1][1] = fmaf(a1.x, w1.x, acc[1][1]); acc[1][1] = fmaf(a1.y, w1.y, acc[1][1]);
        acc[1][1] = fmaf(a1.z, w1.z, acc[1][1]); acc[1][1] = fmaf(a1.w, w1.w, acc[1][1]);
        acc[1][2] = fmaf(a1.x, w2.x, acc[1][2]); acc[1][2] = fmaf(a1.y, w2.y, acc[1][2]);
        acc[1][2] = fmaf(a1.z, w2.z, acc[1][2]); acc[1][2] = fmaf(a1.w, w2.w, acc[1][2]);
        acc[1][3] = fmaf(a1.x, w3.x, acc[1][3]); acc[1][3] = fmaf(a1.y, w3.y, acc[1][3]);
        acc[1][3] = fmaf(a1.z, w3.z, acc[1][3]); acc[1][3] = fmaf(a1.w, w3.w, acc[1][3]);
    }

    // out[p][q] -> dst[q*36 + p] (transposed convention), banks distinct across lanes.
    float* d0 = dst + (2 * sg + 0) * SROW + p;
    float* d1 = dst + (2 * sg + 1) * SROW + p;
#pragma unroll
    for (int j = 0; j < 4; ++j) {
        d0[(qg * 4 + j) * PAD] = acc[0][j];
        d1[(qg * 4 + j) * PAD] = acc[1][j];
    }
}

__global__ void __launch_bounds__(NTHREADS, 1)
monarch_kernel(const float* __restrict__ x,
               const float* __restrict__ L,
               const float* __restrict__ R,
               float* __restrict__ out)
{
    __shared__ float bufA[BATCHPER * SROW];
    __shared__ float bufB[BATCHPER * SROW];

    const int tid = threadIdx.x;
    const int p   = tid & 31;
    const int g   = tid >> 5;       // 0..15
    const int qg  = g & 7;          // q-group of 4
    const int sg  = g >> 3;         // sample pair 0/1
    const int b0  = blockIdx.x * BATCHPER;

    // Load x as float4: h[n][m] = x[n*32+m] stored at buf[n*36 + m] (aligned rows).
    {
        const float4* x4 = reinterpret_cast<const float4*>(x);
        for (int i = tid; i < BATCHPER * 256; i += NTHREADS) {
            int b = i >> 8, t = i & 255;        // t = n*8 + mc
            int n = t >> 3, mc = t & 7;
            *reinterpret_cast<float4*>(bufA + b * SROW + n * PAD + mc * 4) =
                x4[(size_t)(b0 + b) * 256 + t];
        }
    }
    __syncthreads();

    const float* Wl = L;
    const float* Wr = R;
    for (int layer = 0; layer < DEPTH; ++layer) {
        phase(bufA, bufB, Wl, p, qg, sg);
        __syncthreads();
        phase(bufB, bufA, Wr, p, qg, sg);
        __syncthreads();
        Wl += 32768;
        Wr += 32768;
    }

    // Final value for dim d=n*32+m sits at buf[n*36 + m]; store as float4.
    {
        float4* o4 = reinterpret_cast<float4*>(out);
        for (int i = tid; i < BATCHPER * 256; i += NTHREADS) {
            int b = i >> 8, t = i & 255;
            int n = t >> 3, mc = t & 7;
            o4[(size_t)(b0 + b) * 256 + t] =
                *reinterpret_cast<const float4*>(bufA + b * SROW + n * PAD + mc * 4);
        }
    }
}

extern "C" void kernel_launch(void* const* d_in, const int* in_sizes, int n_in,
                              void* d_out, int out_size)
{
    const float* x = (const float*)d_in[0];
    const float* L = (const float*)d_in[1];
    const float* R = (const float*)d_in[2];
    float* out = (float*)d_out;
    monarch_kernel<<<NCTA, NTHREADS>>>(x, L, R, out);
}

// round 3
// speedup vs baseline: 3.0655x; 3.0655x over previous
#include <cuda_runtime.h>
#include <cstdint>

// StructuredDeepLinear: 1000 Monarch layers, DIM=1024 (32 blocks of 32x32), BATCH=512.
//
// Per-CTA: 4 samples resident in SMEM for all 2000 phases. Weights stream
// GMEM -> SMEM via cp.async in coalesced 16B granules with the standard 128B
// XOR swizzle, 32KB chunks (8 p-blocks), ring of 4 buffers, prefetch depth 3.
//
// Compute mapping: lane = q (output col), warp = p-block within chunk.
//   weights:  swizzled LDS.128, bank-group rc ^ (q&7)  -> conflict-free
//   acts:     act[p][r][b0..3] rows; reads are broadcast LDS.128 (all lanes same addr)
//   store:    out[b][p][q] -> dst[q][p][b] as one STS.128 (Monarch transpose folded in);
//             bank-group (q+p)%8 -> conflict-free
//
// Index algebra vs reference:
//   phase1: out[n][k] = sum_m in[n][m] * L[n][k][m]   (p=n, q=k, r=m)
//   transpose: in2[k][n] = out1[n][k]  == dst[q][p] store convention
//   phase2: out[k][j] = sum_n in2[k][n] * R[k][j][n]  (p=k, q=j, r=n)
//   final flatten d = j*32+k == act[j][k][b], same formula as the x load.

#define NTHREADS 256
#define NCTA     128
#define DEPTH    1000
#define NPHASES  (2 * DEPTH)
#define NCHUNKS  (4 * NPHASES)      // 8000
#define CHUNK_FLOATS 8192           // 8 p-blocks * 1024 floats = 32KB
#define RING     4
#define RS       132                // words per p-row: 32 r * 4 b + 4 pad
#define ACT_WORDS (32 * RS)

__device__ __forceinline__ uint32_t smem_u32(const void* p) {
    return (uint32_t)__cvta_generic_to_shared(p);
}

extern __shared__ float wring[];    // RING * CHUNK_FLOATS floats = 128KB

__global__ void __launch_bounds__(NTHREADS, 1)
monarch_kernel(const float* __restrict__ x,
               const float* __restrict__ L,
               const float* __restrict__ R,
               float* __restrict__ out)
{
    __shared__ float actA[ACT_WORDS];
    __shared__ float actB[ACT_WORDS];

    const int tid  = threadIdx.x;
    const int lane = tid & 31;      // q
    const int wid  = tid >> 5;      // 0..7 : p-block within chunk
    const int b0   = blockIdx.x * 4;

    // Load x: h[b][n][m] = x[b][n*32+m] -> actA[n*RS + m*4 + b]
    for (int i = tid; i < 1024; i += NTHREADS) {
        int n = i >> 5, m = i & 31;
#pragma unroll
        for (int b = 0; b < 4; ++b)
            actA[n * RS + m * 4 + b] = x[(size_t)(b0 + b) * 1024 + i];
    }

    const uint32_t ring_base = smem_u32(wring);

    // Coalesced, swizzled chunk prefetch. Granule G (16B) of chunk g:
    //   src: contiguous (perfectly coalesced across tid)
    //   dst: within-p granule w4 = q*8+gsub  ->  w4 ^ ((w4>>3)&7)   (128B XOR swizzle)
    auto prefetch = [&](int g) {
        if (g < NCHUNKS) {
            int phase = g >> 2, c = g & 3;
            const float* base = ((phase & 1) ? R : L)
                              + (size_t)(phase >> 1) * 32768 + c * 8192;
            uint32_t dbase = ring_base + (uint32_t)(g & (RING - 1)) * (CHUNK_FLOATS * 4);
#pragma unroll
            for (int k = 0; k < 8; ++k) {
                int G   = tid + k * NTHREADS;               // 0..2047
                int w4  = G & 255;
                int dG  = (G & ~255) | (w4 ^ ((w4 >> 3) & 7));
                const float* src = base + (size_t)G * 4;
                uint32_t dst = dbase + (uint32_t)dG * 16;
                asm volatile("cp.async.ca.shared.global [%0], [%1], 16;\n"
                             :: "r"(dst), "l"(src));
            }
        }
        asm volatile("cp.async.commit_group;\n");
    };

    prefetch(0); prefetch(1); prefetch(2);

    for (int g = 0; g < NCHUNKS; ++g) {
        asm volatile("cp.async.wait_group 2;\n");
        __syncthreads();                 // chunk g visible to all; prev readers done
        prefetch(g + 3);                 // overwrites buffer of chunk g-1 (safe)

        const int phase = g >> 2;
        const int c     = g & 3;
        const float* src = (phase & 1) ? actB : actA;
        float*       dst = (phase & 1) ? actA : actB;
        const int p = c * 8 + wid;       // this warp's p-block

        const float4* wbase = reinterpret_cast<const float4*>(
            wring + (size_t)(g & (RING - 1)) * CHUNK_FLOATS + wid * 1024);
        const float4* abase = reinterpret_cast<const float4*>(src + p * RS);

        float acc0 = 0.f, acc1 = 0.f, acc2 = 0.f, acc3 = 0.f;
#pragma unroll
        for (int rc = 0; rc < 8; ++rc) {
            // weights W[p][q=lane][4rc..4rc+3], swizzled granule
            float4 w = wbase[(lane * 8 + rc) ^ (lane & 7)];
            // activations (broadcast): A_k = act[p][r=4rc+k][b0..3]
            float4 A0 = abase[rc * 4 + 0];
            float4 A1 = abase[rc * 4 + 1];
            float4 A2 = abase[rc * 4 + 2];
            float4 A3 = abase[rc * 4 + 3];

            acc0 = fmaf(A0.x, w.x, acc0); acc1 = fmaf(A0.y, w.x, acc1);
            acc2 = fmaf(A0.z, w.x, acc2); acc3 = fmaf(A0.w, w.x, acc3);
            acc0 = fmaf(A1.x, w.y, acc0); acc1 = fmaf(A1.y, w.y, acc1);
            acc2 = fmaf(A1.z, w.y, acc2); acc3 = fmaf(A1.w, w.y, acc3);
            acc0 = fmaf(A2.x, w.z, acc0); acc1 = fmaf(A2.y, w.z, acc1);
            acc2 = fmaf(A2.z, w.z, acc2); acc3 = fmaf(A2.w, w.z, acc3);
            acc0 = fmaf(A3.x, w.w, acc0); acc1 = fmaf(A3.y, w.w, acc1);
            acc2 = fmaf(A3.z, w.w, acc2); acc3 = fmaf(A3.w, w.w, acc3);
        }

        // out[b][p][q] -> dst[q][p][b] : one conflict-free STS.128
        *reinterpret_cast<float4*>(dst + lane * RS + p * 4) =
            make_float4(acc0, acc1, acc2, acc3);
    }

    __syncthreads();
    // Final: out[b][j*32+k] = actA[j][k][b]  (2000 phases -> result in actA)
    for (int i = tid; i < 1024; i += NTHREADS) {
        int n = i >> 5, m = i & 31;
#pragma unroll
        for (int b = 0; b < 4; ++b)
            out[(size_t)(b0 + b) * 1024 + i] = actA[n * RS + m * 4 + b];
    }
}

extern "C" void kernel_launch(void* const* d_in, const int* in_sizes, int n_in,
                              void* d_out, int out_size)
{
    const float* x = (const float*)d_in[0];
    const float* L = (const float*)d_in[1];
    const float* R = (const float*)d_in[2];
    float* out = (float*)d_out;

    cudaFuncSetAttribute(monarch_kernel,
                         cudaFuncAttributeMaxDynamicSharedMemorySize,
                         RING * CHUNK_FLOATS * sizeof(float));
    monarch_kernel<<<NCTA, NTHREADS, RING * CHUNK_FLOATS * sizeof(float)>>>(x, L, R, out);
}

// round 4
// speedup vs baseline: 7.7509x; 2.5284x over previous
#include <cuda_runtime.h>
#include <cstdint>

// StructuredDeepLinear: 1000 Monarch layers, DIM=1024 (32 blocks of 32x32), BATCH=512.
//
// Per-CTA: 4 samples resident in SMEM (layout act[p][r][b0..3], row stride RS=132,
// 16B-aligned, conflict-free for broadcast reads and transposed STS.128 writes).
// Weights stream GMEM -> SMEM via cp.async.cg in coalesced, 128B-XOR-swizzled 16B
// granules; 64KB half-phase chunks; ring of 3; ONE __syncthreads per chunk.
//
// Compute: lane = q, warp = p-block (16 warps, 16 p-blocks per chunk).
//   weights: swizzled LDS.128 (conflict-free), acts: broadcast LDS.128,
//   math: fma.rn.f32x2 (acc/act pairs over samples b; weight scalar dup'd via mov.b64),
//   store: out[p][q][b] -> dst[q*RS + p*4 + b] as one conflict-free STS.128
//          (Monarch block-transpose folded into addressing).

#define NTHREADS 512
#define NCTA     128
#define DEPTH    1000
#define NCHUNKS  (2 * DEPTH)        // 64KB half-phase chunks
#define CHUNK_FLOATS 16384          // 16 p-blocks * 1024 floats = 64KB
#define RING     3
#define RS       132                // words per p-row: 32 r * 4 b + 4 pad
#define ACT_WORDS (32 * RS)

__device__ __forceinline__ uint32_t smem_u32(const void* p) {
    return (uint32_t)__cvta_generic_to_shared(p);
}
__device__ __forceinline__ unsigned long long dup2(float s) {
    unsigned long long r;
    unsigned u = __float_as_uint(s);
    asm("mov.b64 %0, {%1, %1};" : "=l"(r) : "r"(u));
    return r;
}
__device__ __forceinline__ void fma2(unsigned long long& acc,
                                     unsigned long long a,
                                     unsigned long long w) {
    asm("fma.rn.f32x2 %0, %1, %2, %0;" : "+l"(acc) : "l"(a), "l"(w));
}

extern __shared__ float wring[];    // RING * CHUNK_FLOATS floats = 192KB dynamic

__global__ void __launch_bounds__(NTHREADS, 1)
monarch_kernel(const float* __restrict__ x,
               const float* __restrict__ L,
               const float* __restrict__ R,
               float* __restrict__ out)
{
    __shared__ float actA[ACT_WORDS];   // 16.5KB each
    __shared__ float actB[ACT_WORDS];

    const int tid  = threadIdx.x;
    const int lane = tid & 31;      // q
    const int wid  = tid >> 5;      // 0..15 : p-block within half-phase chunk
    const int b0   = blockIdx.x * 4;

    const uint32_t ring_base = smem_u32(wring);

    // Coalesced, swizzled chunk prefetch (64KB = 4096 granules of 16B).
    auto prefetch = [&](int g) {
        if (g < NCHUNKS) {
            int phase = g >> 1, half = g & 1;
            const float* base = ((phase & 1) ? R : L)
                              + (size_t)(phase >> 1) * 32768 + half * CHUNK_FLOATS;
            uint32_t dbase = ring_base + (uint32_t)(g % RING) * (CHUNK_FLOATS * 4);
#pragma unroll
            for (int k = 0; k < 8; ++k) {
                int G   = tid + k * NTHREADS;               // 0..4095
                int w4  = G & 255;                          // granule within p-block
                int dG  = (G & ~255) | (w4 ^ ((w4 >> 3) & 7));
                const float* src = base + (size_t)G * 4;
                uint32_t dst = dbase + (uint32_t)dG * 16;
                asm volatile("cp.async.cg.shared.global [%0], [%1], 16;\n"
                             :: "r"(dst), "l"(src));
            }
        }
        asm volatile("cp.async.commit_group;\n");
    };

    prefetch(0); prefetch(1);

    // Load x: h[b][n][m] = x[b][n*32+m] -> actA[n*RS + m*4 + b]
    for (int i = tid; i < 1024; i += NTHREADS) {
        int n = i >> 5, m = i & 31;
#pragma unroll
        for (int b = 0; b < 4; ++b)
            actA[n * RS + m * 4 + b] = x[(size_t)(b0 + b) * 1024 + i];
    }

    for (int g = 0; g < NCHUNKS; ++g) {
        asm volatile("cp.async.wait_group 1;\n");   // chunk g resident
        __syncthreads();                            // + everyone done with chunk g-1
        prefetch(g + 2);                            // overwrites buffer of chunk g-1

        const int phase = g >> 1;
        const int half  = g & 1;
        const float* src = (phase & 1) ? actB : actA;
        float*       dst = (phase & 1) ? actA : actB;
        const int p = half * 16 + wid;              // this warp's p-block

        const float4* wbase = reinterpret_cast<const float4*>(
            wring + (size_t)(g % RING) * CHUNK_FLOATS + wid * 1024);
        const ulonglong2* abase = reinterpret_cast<const ulonglong2*>(src + p * RS);

        unsigned long long acc01 = 0ull, acc23 = 0ull;
#pragma unroll
        for (int rc = 0; rc < 8; ++rc) {
            // weights W[p][q=lane][4rc..4rc+3] (swizzled granule), conflict-free
            float4 w = wbase[(lane * 8 + rc) ^ (lane & 7)];
            // activations (broadcast, packed pairs over b): A_k = act[p][4rc+k][b0..3]
            ulonglong2 A0 = abase[rc * 4 + 0];
            ulonglong2 A1 = abase[rc * 4 + 1];
            ulonglong2 A2 = abase[rc * 4 + 2];
            ulonglong2 A3 = abase[rc * 4 + 3];

            unsigned long long w0 = dup2(w.x), w1 = dup2(w.y),
                               w2 = dup2(w.z), w3 = dup2(w.w);
            fma2(acc01, A0.x, w0); fma2(acc23, A0.y, w0);
            fma2(acc01, A1.x, w1); fma2(acc23, A1.y, w1);
            fma2(acc01, A2.x, w2); fma2(acc23, A2.y, w2);
            fma2(acc01, A3.x, w3); fma2(acc23, A3.y, w3);
        }

        // out[p][q][b] -> dst[q][p][b] : one conflict-free STS.128
        ulonglong2 o; o.x = acc01; o.y = acc23;
        *reinterpret_cast<ulonglong2*>(dst + lane * RS + p * 4) = o;
    }

    __syncthreads();
    // Final: out[b][n*32+m] = actA[n][m][b]  (2000 phases -> result in actA)
    for (int i = tid; i < 1024; i += NTHREADS) {
        int n = i >> 5, m = i & 31;
#pragma unroll
        for (int b = 0; b < 4; ++b)
            out[(size_t)(b0 + b) * 1024 + i] = actA[n * RS + m * 4 + b];
    }
}

extern "C" void kernel_launch(void* const* d_in, const int* in_sizes, int n_in,
                              void* d_out, int out_size)
{
    const float* x = (const float*)d_in[0];
    const float* L = (const float*)d_in[1];
    const float* R = (const float*)d_in[2];
    float* out = (float*)d_out;

    cudaFuncSetAttribute(monarch_kernel,
                         cudaFuncAttributeMaxDynamicSharedMemorySize,
                         RING * CHUNK_FLOATS * sizeof(float));
    monarch_kernel<<<NCTA, NTHREADS, RING * CHUNK_FLOATS * sizeof(float)>>>(x, L, R, out);
}